// round 7
// baseline (speedup 1.0000x reference)
#include <cuda_runtime.h>
#include <cuda_fp16.h>
#include <cstdint>

#define NUM_USER  200000
#define NUM_GROUP 50000
#define NROWS     (NUM_USER + NUM_GROUP)   // 250000
#define EDGES     4000000
#define DD        64
#define BB        8192

__device__ __forceinline__ int h2_as_int(__half2 h) {
    return *reinterpret_cast<int*>(&h);
}

// ---- scratch (__device__ globals; no cudaMalloc allowed) -------------------
__device__ __half g_e0[(size_t)NROWS * DD];   // fp16 concat(tables)
__device__ __half g_e1[(size_t)NROWS * DD];
__device__ __half g_e2[(size_t)NROWS * DD];
__device__ __half g_e3[(size_t)NROWS * DD];
__device__ signed char g_q[(size_t)NROWS * DD];  // int8 source (reused L2 & L3)
__device__ int    g_maxbits[2];               // max|e1|, max|e2| as float bits
__device__ int2   g_pairs[EDGES];             // (col, val-bits) sorted by row
__device__ int    g_counts[NROWS];
__device__ int    g_row_ptr[NROWS + 1];
__device__ int    g_cursor[NROWS];

#define SCAN_ELEMS 2048
#define NBLK_SCAN  ((NROWS + SCAN_ELEMS - 1) / SCAN_ELEMS)   // 123
__device__ int   g_blocksums[NBLK_SCAN];
__device__ int   g_blockoff [NBLK_SCAN];

// ---------------------------------------------------------------------------
// 0) convert fp32 tables -> fp16 concat buffer; zero histogram + maxbits
// ---------------------------------------------------------------------------
__global__ __launch_bounds__(256)
void convert_kernel(const float4* __restrict__ ut, const float4* __restrict__ gt)
{
    int i = blockIdx.x * blockDim.x + threadIdx.x;   // one int4 (8 halves)
    if (i < NROWS) g_counts[i] = 0;
    if (i < 2)     g_maxbits[i] = 0;
    if (i >= NROWS * 8) return;
    const int USER8 = NUM_USER * 8;
    float4 lo, hi;
    if (i < USER8) { lo = ut[(size_t)i * 2]; hi = ut[(size_t)i * 2 + 1]; }
    else { size_t j = i - USER8; lo = gt[j * 2]; hi = gt[j * 2 + 1]; }
    int4 o;
    o.x = h2_as_int(__floats2half2_rn(lo.x, lo.y));
    o.y = h2_as_int(__floats2half2_rn(lo.z, lo.w));
    o.z = h2_as_int(__floats2half2_rn(hi.x, hi.y));
    o.w = h2_as_int(__floats2half2_rn(hi.z, hi.w));
    reinterpret_cast<int4*>(g_e0)[i] = o;
}

// ---------------------------------------------------------------------------
// 1) histogram rows (int4-vectorized read)
// ---------------------------------------------------------------------------
__global__ __launch_bounds__(256)
void hist_kernel(const int4* __restrict__ rows4)
{
    int i = blockIdx.x * blockDim.x + threadIdx.x;
    if (i >= EDGES / 4) return;
    int4 r = rows4[i];
    atomicAdd(&g_counts[r.x], 1);
    atomicAdd(&g_counts[r.y], 1);
    atomicAdd(&g_counts[r.z], 1);
    atomicAdd(&g_counts[r.w], 1);
}

// ---------------------------------------------------------------------------
// 2a) per-block sums of counts
// ---------------------------------------------------------------------------
__global__ __launch_bounds__(256)
void scan1_kernel()
{
    __shared__ int sh[256];
    int tid  = threadIdx.x;
    int base = blockIdx.x * SCAN_ELEMS + tid * 8;
    int s = 0;
    #pragma unroll
    for (int j = 0; j < 8; j++) {
        int i = base + j;
        s += (i < NROWS) ? g_counts[i] : 0;
    }
    sh[tid] = s;
    __syncthreads();
    for (int off = 128; off > 0; off >>= 1) {
        if (tid < off) sh[tid] += sh[tid + off];
        __syncthreads();
    }
    if (tid == 0) g_blocksums[blockIdx.x] = sh[0];
}

// 2b) exclusive scan of 123 block sums (one block, parallel)
__global__ __launch_bounds__(128)
void scan2_kernel()
{
    __shared__ int sh[128];
    int tid = threadIdx.x;
    int v = (tid < NBLK_SCAN) ? g_blocksums[tid] : 0;
    sh[tid] = v;
    __syncthreads();
    for (int off = 1; off < 128; off <<= 1) {
        int t = (tid >= off) ? sh[tid - off] : 0;
        __syncthreads();
        sh[tid] += t;
        __syncthreads();
    }
    if (tid < NBLK_SCAN) g_blockoff[tid] = sh[tid] - v;
}

// 2c) intra-block exclusive scan + offset -> row_ptr & cursor
__global__ __launch_bounds__(256)
void scan3_kernel()
{
    __shared__ int sh[256];
    int tid  = threadIdx.x;
    int base = blockIdx.x * SCAN_ELEMS + tid * 8;
    int v[8];
    int s = 0;
    #pragma unroll
    for (int j = 0; j < 8; j++) {
        int i = base + j;
        v[j] = (i < NROWS) ? g_counts[i] : 0;
        s += v[j];
    }
    sh[tid] = s;
    __syncthreads();
    for (int off = 1; off < 256; off <<= 1) {
        int t = (tid >= off) ? sh[tid - off] : 0;
        __syncthreads();
        sh[tid] += t;
        __syncthreads();
    }
    int excl = sh[tid] - s;
    int run  = g_blockoff[blockIdx.x] + excl;
    #pragma unroll
    for (int j = 0; j < 8; j++) {
        int i = base + j;
        if (i < NROWS) { g_row_ptr[i] = run; g_cursor[i] = run; }
        run += v[j];
    }
    if (blockIdx.x == 0 && tid == 0) g_row_ptr[NROWS] = EDGES;
}

// ---------------------------------------------------------------------------
// 3) scatter edges into row-sorted order (scalar — R4 known-good form)
// ---------------------------------------------------------------------------
__global__ __launch_bounds__(256)
void scatter_kernel(const int* __restrict__ rows, const int* __restrict__ cols,
                    const float* __restrict__ vals)
{
    int e = blockIdx.x * blockDim.x + threadIdx.x;
    if (e >= EDGES) return;
    int r   = rows[e];
    int pos = atomicAdd(&g_cursor[r], 1);
    g_pairs[pos] = make_int2(cols[e], __float_as_int(vals[e]));
}

// ---------------------------------------------------------------------------
// 4a) spmm layer 1: fp16 src, fp32 accumulate, fp16 dst, block-max -> maxbits[0]
//     8 threads per row; each owns 8 halves. Unroll 2 (R4 known-good form).
// ---------------------------------------------------------------------------
__device__ __forceinline__ void acc_fma8(float* a, int4 x, float v)
{
    __half2* h = reinterpret_cast<__half2*>(&x);
    #pragma unroll
    for (int i = 0; i < 4; i++) {
        float2 f = __half22float2(h[i]);
        a[2*i]   = fmaf(v, f.x, a[2*i]);
        a[2*i+1] = fmaf(v, f.y, a[2*i+1]);
    }
}

__global__ __launch_bounds__(256)
void spmm_h_kernel(const int4* __restrict__ src, int4* __restrict__ dst,
                   int max_out_idx)
{
    int t    = blockIdx.x * blockDim.x + threadIdx.x;
    int r    = t >> 3;
    int lane = t & 7;
    bool valid = (r < NROWS);

    float a[8];
    #pragma unroll
    for (int k = 0; k < 8; k++) a[k] = 0.f;

    if (valid) {
        int p  = __ldg(&g_row_ptr[r]);
        int pe = __ldg(&g_row_ptr[r + 1]);
        for (; p + 2 <= pe; p += 2) {
            int2 q0 = __ldg(&g_pairs[p]);
            int2 q1 = __ldg(&g_pairs[p + 1]);
            int4 x0 = __ldg(&src[(size_t)q0.x * 8 + lane]);
            int4 x1 = __ldg(&src[(size_t)q1.x * 8 + lane]);
            acc_fma8(a, x0, __int_as_float(q0.y));
            acc_fma8(a, x1, __int_as_float(q1.y));
        }
        if (p < pe) {
            int2 q0 = __ldg(&g_pairs[p]);
            int4 x0 = __ldg(&src[(size_t)q0.x * 8 + lane]);
            acc_fma8(a, x0, __int_as_float(q0.y));
        }
        int4 o;
        o.x = h2_as_int(__floats2half2_rn(a[0], a[1]));
        o.y = h2_as_int(__floats2half2_rn(a[2], a[3]));
        o.z = h2_as_int(__floats2half2_rn(a[4], a[5]));
        o.w = h2_as_int(__floats2half2_rn(a[6], a[7]));
        dst[(size_t)r * 8 + lane] = o;
    }

    // block max |a| -> global atomicMax (float bits, values >= 0)
    __shared__ float smax[256];
    float m = 0.f;
    #pragma unroll
    for (int k = 0; k < 8; k++) m = fmaxf(m, fabsf(a[k]));
    smax[threadIdx.x] = m;
    __syncthreads();
    for (int off = 128; off > 0; off >>= 1) {
        if (threadIdx.x < off)
            smax[threadIdx.x] = fmaxf(smax[threadIdx.x], smax[threadIdx.x + off]);
        __syncthreads();
    }
    if (threadIdx.x == 0)
        atomicMax(&g_maxbits[max_out_idx], __float_as_int(smax[0]));
}

// ---------------------------------------------------------------------------
// 4b) quantize fp16 buffer -> int8 with global scale 127/max
// ---------------------------------------------------------------------------
__global__ __launch_bounds__(256)
void quant_kernel(const int4* __restrict__ src_h, int2* __restrict__ dst_q,
                  int max_idx)
{
    int i = blockIdx.x * blockDim.x + threadIdx.x;   // one chunk of 8 halves
    if (i >= NROWS * 8) return;
    float mx = __int_as_float(g_maxbits[max_idx]);
    float k  = 127.0f / mx;
    int4 h = __ldg(&src_h[i]);
    __half2* hh = reinterpret_cast<__half2*>(&h);
    int b[8];
    #pragma unroll
    for (int j = 0; j < 4; j++) {
        float2 f = __half22float2(hh[j]);
        float f0 = fminf(fmaxf(f.x * k, -127.f), 127.f);
        float f1 = fminf(fmaxf(f.y * k, -127.f), 127.f);
        b[2*j]   = __float2int_rn(f0);
        b[2*j+1] = __float2int_rn(f1);
    }
    int w0 = (b[0] & 0xff) | ((b[1] & 0xff) << 8) | ((b[2] & 0xff) << 16) | (b[3] << 24);
    int w1 = (b[4] & 0xff) | ((b[5] & 0xff) << 8) | ((b[6] & 0xff) << 16) | (b[7] << 24);
    dst_q[i] = make_int2(w0, w1);
}

// ---------------------------------------------------------------------------
// 4c) spmm layers 2/3: int8 src (64 B/row), fp32 accumulate, fp16 dst.
//     Optionally computes max for the next quantization.
// ---------------------------------------------------------------------------
__device__ __forceinline__ void acc_i8(float* a, int2 x, float v)
{
    int w0 = x.x, w1 = x.y;
    a[0] = fmaf(v, (float)((w0 << 24) >> 24), a[0]);
    a[1] = fmaf(v, (float)((w0 << 16) >> 24), a[1]);
    a[2] = fmaf(v, (float)((w0 <<  8) >> 24), a[2]);
    a[3] = fmaf(v, (float)( w0        >> 24), a[3]);
    a[4] = fmaf(v, (float)((w1 << 24) >> 24), a[4]);
    a[5] = fmaf(v, (float)((w1 << 16) >> 24), a[5]);
    a[6] = fmaf(v, (float)((w1 <<  8) >> 24), a[6]);
    a[7] = fmaf(v, (float)( w1        >> 24), a[7]);
}

template <bool COMPUTE_MAX>
__global__ __launch_bounds__(256)
void spmm_q_kernel(const int2* __restrict__ src_q, int4* __restrict__ dst,
                   int scale_in_idx, int max_out_idx)
{
    int t    = blockIdx.x * blockDim.x + threadIdx.x;
    int r    = t >> 3;
    int lane = t & 7;
    bool valid = (r < NROWS);
    if (!COMPUTE_MAX && !valid) return;

    float a[8];
    #pragma unroll
    for (int k = 0; k < 8; k++) a[k] = 0.f;

    if (valid) {
        int p  = __ldg(&g_row_ptr[r]);
        int pe = __ldg(&g_row_ptr[r + 1]);
        for (; p + 2 <= pe; p += 2) {
            int2 q0 = __ldg(&g_pairs[p]);
            int2 q1 = __ldg(&g_pairs[p + 1]);
            int2 x0 = __ldg(&src_q[(size_t)q0.x * 8 + lane]);
            int2 x1 = __ldg(&src_q[(size_t)q1.x * 8 + lane]);
            acc_i8(a, x0, __int_as_float(q0.y));
            acc_i8(a, x1, __int_as_float(q1.y));
        }
        if (p < pe) {
            int2 q0 = __ldg(&g_pairs[p]);
            int2 x0 = __ldg(&src_q[(size_t)q0.x * 8 + lane]);
            acc_i8(a, x0, __int_as_float(q0.y));
        }
        float s = __int_as_float(g_maxbits[scale_in_idx]) * (1.0f / 127.0f);
        #pragma unroll
        for (int k = 0; k < 8; k++) a[k] *= s;

        int4 o;
        o.x = h2_as_int(__floats2half2_rn(a[0], a[1]));
        o.y = h2_as_int(__floats2half2_rn(a[2], a[3]));
        o.z = h2_as_int(__floats2half2_rn(a[4], a[5]));
        o.w = h2_as_int(__floats2half2_rn(a[6], a[7]));
        dst[(size_t)r * 8 + lane] = o;
    }

    if (COMPUTE_MAX) {
        __shared__ float smax[256];
        float m = 0.f;
        #pragma unroll
        for (int k = 0; k < 8; k++) m = fmaxf(m, fabsf(a[k]));
        smax[threadIdx.x] = m;
        __syncthreads();
        for (int off = 128; off > 0; off >>= 1) {
            if (threadIdx.x < off)
                smax[threadIdx.x] = fmaxf(smax[threadIdx.x], smax[threadIdx.x + off]);
            __syncthreads();
        }
        if (threadIdx.x == 0)
            atomicMax(&g_maxbits[max_out_idx], __float_as_int(smax[0]));
    }
}

// ---------------------------------------------------------------------------
// 5) final six-way gather: (emb0 + e1 + e2 + e3)/4 on the fly (all fp16 exactish)
// ---------------------------------------------------------------------------
__device__ __forceinline__ float4 load_h4(const __half* base, size_t row, int lane)
{
    uint2 u = __ldg(reinterpret_cast<const uint2*>(base + row * DD) + lane);
    __half2 h0 = *reinterpret_cast<__half2*>(&u.x);
    __half2 h1 = *reinterpret_cast<__half2*>(&u.y);
    float2 f0 = __half22float2(h0);
    float2 f1 = __half22float2(h1);
    return make_float4(f0.x, f0.y, f1.x, f1.y);
}

__global__ __launch_bounds__(256)
void gather_kernel(const float4* __restrict__ ut, const float4* __restrict__ gt,
                   const int* __restrict__ ui, const int* __restrict__ pg,
                   const int* __restrict__ ng, float4* __restrict__ out)
{
    int t = blockIdx.x * blockDim.x + threadIdx.x;
    if (t >= BB * 16) return;
    int b    = t >> 4;
    int lane = t & 15;

    int u = ui[b];
    size_t gp = (size_t)NUM_USER + pg[b];
    size_t gn = (size_t)NUM_USER + ng[b];

    const float s = 0.25f;

    {
        float4 t0 = ut[(size_t)u * 16 + lane];
        float4 f1 = load_h4(g_e1, (size_t)u, lane);
        float4 f2 = load_h4(g_e2, (size_t)u, lane);
        float4 f3 = load_h4(g_e3, (size_t)u, lane);
        out[((size_t)0 * BB + b) * 16 + lane] = make_float4(
            (t0.x + f1.x + f2.x + f3.x) * s, (t0.y + f1.y + f2.y + f3.y) * s,
            (t0.z + f1.z + f2.z + f3.z) * s, (t0.w + f1.w + f2.w + f3.w) * s);
        out[((size_t)3 * BB + b) * 16 + lane] = t0;
    }
    {
        float4 t0 = gt[(gp - NUM_USER) * 16 + lane];
        float4 f1 = load_h4(g_e1, gp, lane);
        float4 f2 = load_h4(g_e2, gp, lane);
        float4 f3 = load_h4(g_e3, gp, lane);
        out[((size_t)1 * BB + b) * 16 + lane] = make_float4(
            (t0.x + f1.x + f2.x + f3.x) * s, (t0.y + f1.y + f2.y + f3.y) * s,
            (t0.z + f1.z + f2.z + f3.z) * s, (t0.w + f1.w + f2.w + f3.w) * s);
        out[((size_t)4 * BB + b) * 16 + lane] = t0;
    }
    {
        float4 t0 = gt[(gn - NUM_USER) * 16 + lane];
        float4 f1 = load_h4(g_e1, gn, lane);
        float4 f2 = load_h4(g_e2, gn, lane);
        float4 f3 = load_h4(g_e3, gn, lane);
        out[((size_t)2 * BB + b) * 16 + lane] = make_float4(
            (t0.x + f1.x + f2.x + f3.x) * s, (t0.y + f1.y + f2.y + f3.y) * s,
            (t0.z + f1.z + f2.z + f3.z) * s, (t0.w + f1.w + f2.w + f3.w) * s);
        out[((size_t)5 * BB + b) * 16 + lane] = t0;
    }
}

// ---------------------------------------------------------------------------
extern "C" void kernel_launch(void* const* d_in, const int* in_sizes, int n_in,
                              void* d_out, int out_size)
{
    const float* user_table  = (const float*)d_in[0];
    const float* group_table = (const float*)d_in[1];
    const float* adj_vals    = (const float*)d_in[2];
    const int*   rows        = (const int*)  d_in[3];
    const int*   cols        = (const int*)  d_in[4];
    const int*   user_inputs = (const int*)  d_in[5];
    const int*   pos_groups  = (const int*)  d_in[6];
    const int*   neg_groups  = (const int*)  d_in[7];

    __half* e0 = nullptr, * e1 = nullptr, * e2 = nullptr, * e3 = nullptr;
    signed char* q = nullptr;
    cudaGetSymbolAddress((void**)&e0, g_e0);
    cudaGetSymbolAddress((void**)&e1, g_e1);
    cudaGetSymbolAddress((void**)&e2, g_e2);
    cudaGetSymbolAddress((void**)&e3, g_e3);
    cudaGetSymbolAddress((void**)&q,  g_q);

    const int TB = 256;

    convert_kernel<<<(NROWS * 8 + TB - 1) / TB, TB>>>(
        (const float4*)user_table, (const float4*)group_table);

    hist_kernel<<<(EDGES / 4 + TB - 1) / TB, TB>>>((const int4*)rows);
    scan1_kernel<<<NBLK_SCAN, TB>>>();
    scan2_kernel<<<1, 128>>>();
    scan3_kernel<<<NBLK_SCAN, TB>>>();
    scatter_kernel<<<(EDGES + TB - 1) / TB, TB>>>(rows, cols, adj_vals);

    const int grid_spmm = (NROWS * 8 + TB - 1) / TB;   // 7813

    // L1: e1 = A*e0 (fp16 src), max|e1| -> maxbits[0]
    spmm_h_kernel<<<grid_spmm, TB>>>((const int4*)e0, (int4*)e1, 0);
    // quantize e1 -> q with scale maxbits[0]
    quant_kernel<<<grid_spmm, TB>>>((const int4*)e1, (int2*)q, 0);
    // L2: e2 = A*e1 (int8 src, scale 0), max|e2| -> maxbits[1]
    spmm_q_kernel<true><<<grid_spmm, TB>>>((const int2*)q, (int4*)e2, 0, 1);
    // quantize e2 -> q with scale maxbits[1]
    quant_kernel<<<grid_spmm, TB>>>((const int4*)e2, (int2*)q, 1);
    // L3: e3 = A*e2 (int8 src, scale 1)
    spmm_q_kernel<false><<<grid_spmm, TB>>>((const int2*)q, (int4*)e3, 1, 0);

    gather_kernel<<<(BB * 16 + TB - 1) / TB, TB>>>(
        (const float4*)user_table, (const float4*)group_table,
        user_inputs, pos_groups, neg_groups, (float4*)d_out);
}

// round 8
// speedup vs baseline: 1.1418x; 1.1418x over previous
#include <cuda_runtime.h>
#include <cuda_fp16.h>
#include <cstdint>

#define NUM_USER  200000
#define NUM_GROUP 50000
#define NROWS     (NUM_USER + NUM_GROUP)   // 250000
#define EDGES     4000000
#define DD        64
#define BB        8192

__device__ __forceinline__ int h2_as_int(__half2 h) {
    return *reinterpret_cast<int*>(&h);
}

// ---- scratch (__device__ globals; no cudaMalloc allowed) -------------------
__device__ __half g_e0[(size_t)NROWS * DD];   // fp16 concat(tables)
__device__ __half g_e1[(size_t)NROWS * DD];
__device__ __half g_e2[(size_t)NROWS * DD];
__device__ __half g_e3[(size_t)NROWS * DD];
__device__ int2   g_pairs[EDGES];             // (col, val-bits) sorted by row
__device__ int    g_counts[NROWS];
__device__ int    g_row_ptr[NROWS + 1];
__device__ int    g_cursor[NROWS];
__device__ int    g_s1done;

#define SCAN_ELEMS 2048
#define NBLK_SCAN  ((NROWS + SCAN_ELEMS - 1) / SCAN_ELEMS)   // 123
__device__ int   g_blocksums[NBLK_SCAN];
__device__ int   g_blockoff [NBLK_SCAN];

// ---------------------------------------------------------------------------
// 0) convert fp32 tables -> fp16 concat buffer; zero histogram + ticket
// ---------------------------------------------------------------------------
__global__ __launch_bounds__(256)
void convert_kernel(const float4* __restrict__ ut, const float4* __restrict__ gt)
{
    int i = blockIdx.x * blockDim.x + threadIdx.x;   // one int4 (8 halves)
    if (i < NROWS) g_counts[i] = 0;
    if (i == 0)    g_s1done = 0;
    if (i >= NROWS * 8) return;
    const int USER8 = NUM_USER * 8;
    float4 lo, hi;
    if (i < USER8) { lo = ut[(size_t)i * 2]; hi = ut[(size_t)i * 2 + 1]; }
    else { size_t j = i - USER8; lo = gt[j * 2]; hi = gt[j * 2 + 1]; }
    int4 o;
    o.x = h2_as_int(__floats2half2_rn(lo.x, lo.y));
    o.y = h2_as_int(__floats2half2_rn(lo.z, lo.w));
    o.z = h2_as_int(__floats2half2_rn(hi.x, hi.y));
    o.w = h2_as_int(__floats2half2_rn(hi.z, hi.w));
    reinterpret_cast<int4*>(g_e0)[i] = o;
}

// ---------------------------------------------------------------------------
// 1) histogram rows (int4-vectorized read)
// ---------------------------------------------------------------------------
__global__ __launch_bounds__(256)
void hist_kernel(const int4* __restrict__ rows4)
{
    int i = blockIdx.x * blockDim.x + threadIdx.x;
    if (i >= EDGES / 4) return;
    int4 r = rows4[i];
    atomicAdd(&g_counts[r.x], 1);
    atomicAdd(&g_counts[r.y], 1);
    atomicAdd(&g_counts[r.z], 1);
    atomicAdd(&g_counts[r.w], 1);
}

// ---------------------------------------------------------------------------
// 2a) per-block sums + (last block via ticket) scan of the 123 block sums
// ---------------------------------------------------------------------------
__global__ __launch_bounds__(256)
void scan1_kernel()
{
    __shared__ int sh[256];
    __shared__ int sh_last;
    int tid  = threadIdx.x;
    int base = blockIdx.x * SCAN_ELEMS + tid * 8;
    int s = 0;
    #pragma unroll
    for (int j = 0; j < 8; j++) {
        int i = base + j;
        s += (i < NROWS) ? g_counts[i] : 0;
    }
    sh[tid] = s;
    __syncthreads();
    for (int off = 128; off > 0; off >>= 1) {
        if (tid < off) sh[tid] += sh[tid + off];
        __syncthreads();
    }
    if (tid == 0) {
        g_blocksums[blockIdx.x] = sh[0];
        __threadfence();
        int t = atomicAdd(&g_s1done, 1);
        sh_last = (t == gridDim.x - 1);
    }
    __syncthreads();
    if (sh_last) {
        __shared__ int sc[128];
        if (tid < 128) {
            int v = (tid < NBLK_SCAN) ? g_blocksums[tid] : 0;
            sc[tid] = v;
            __syncthreads();
            for (int off = 1; off < 128; off <<= 1) {
                int t2 = (tid >= off) ? sc[tid - off] : 0;
                __syncthreads();
                sc[tid] += t2;
                __syncthreads();
            }
            if (tid < NBLK_SCAN) g_blockoff[tid] = sc[tid] - v;
        }
    }
}

// 2b) intra-block exclusive scan + offset -> row_ptr & cursor
__global__ __launch_bounds__(256)
void scan3_kernel()
{
    __shared__ int sh[256];
    int tid  = threadIdx.x;
    int base = blockIdx.x * SCAN_ELEMS + tid * 8;
    int v[8];
    int s = 0;
    #pragma unroll
    for (int j = 0; j < 8; j++) {
        int i = base + j;
        v[j] = (i < NROWS) ? g_counts[i] : 0;
        s += v[j];
    }
    sh[tid] = s;
    __syncthreads();
    for (int off = 1; off < 256; off <<= 1) {
        int t = (tid >= off) ? sh[tid - off] : 0;
        __syncthreads();
        sh[tid] += t;
        __syncthreads();
    }
    int excl = sh[tid] - s;
    int run  = g_blockoff[blockIdx.x] + excl;
    #pragma unroll
    for (int j = 0; j < 8; j++) {
        int i = base + j;
        if (i < NROWS) { g_row_ptr[i] = run; g_cursor[i] = run; }
        run += v[j];
    }
    if (blockIdx.x == 0 && tid == 0) g_row_ptr[NROWS] = EDGES;
}

// ---------------------------------------------------------------------------
// 3) scatter edges into row-sorted order (scalar — R4 known-good form)
// ---------------------------------------------------------------------------
__global__ __launch_bounds__(256)
void scatter_kernel(const int* __restrict__ rows, const int* __restrict__ cols,
                    const float* __restrict__ vals)
{
    int e = blockIdx.x * blockDim.x + threadIdx.x;
    if (e >= EDGES) return;
    int r   = rows[e];
    int pos = atomicAdd(&g_cursor[r], 1);
    g_pairs[pos] = make_int2(cols[e], __float_as_int(vals[e]));
}

// ---------------------------------------------------------------------------
// 4) CSR spmm, fp16 storage / fp32 accumulation (R4 known-good form).
//    8 threads per row; each owns 8 halves (one int4). Unroll 2.
//    dst stored with evict-first so the src table + pairs stay L2-resident.
// ---------------------------------------------------------------------------
__device__ __forceinline__ void acc_fma8(float* a, int4 x, float v)
{
    __half2* h = reinterpret_cast<__half2*>(&x);
    #pragma unroll
    for (int i = 0; i < 4; i++) {
        float2 f = __half22float2(h[i]);
        a[2*i]   = fmaf(v, f.x, a[2*i]);
        a[2*i+1] = fmaf(v, f.y, a[2*i+1]);
    }
}

__global__ __launch_bounds__(256)
void spmm_csr_h_kernel(const int4* __restrict__ src, int4* __restrict__ dst)
{
    int t    = blockIdx.x * blockDim.x + threadIdx.x;
    int r    = t >> 3;
    int lane = t & 7;
    if (r >= NROWS) return;

    int p  = g_row_ptr[r];
    int pe = g_row_ptr[r + 1];

    float a[8];
    #pragma unroll
    for (int i = 0; i < 8; i++) a[i] = 0.f;

    for (; p + 2 <= pe; p += 2) {
        int2 q0 = __ldg(&g_pairs[p]);
        int2 q1 = __ldg(&g_pairs[p + 1]);
        int4 x0 = __ldg(&src[(size_t)q0.x * 8 + lane]);
        int4 x1 = __ldg(&src[(size_t)q1.x * 8 + lane]);
        acc_fma8(a, x0, __int_as_float(q0.y));
        acc_fma8(a, x1, __int_as_float(q1.y));
    }
    if (p < pe) {
        int2 q0 = __ldg(&g_pairs[p]);
        int4 x0 = __ldg(&src[(size_t)q0.x * 8 + lane]);
        acc_fma8(a, x0, __int_as_float(q0.y));
    }

    int4 o;
    o.x = h2_as_int(__floats2half2_rn(a[0], a[1]));
    o.y = h2_as_int(__floats2half2_rn(a[2], a[3]));
    o.z = h2_as_int(__floats2half2_rn(a[4], a[5]));
    o.w = h2_as_int(__floats2half2_rn(a[6], a[7]));
    __stcs(&dst[(size_t)r * 8 + lane], o);   // evict-first: protect src/pairs in L2
}

// ---------------------------------------------------------------------------
// 5) final six-way gather: (emb0 + e1 + e2 + e3)/4 on the fly
// ---------------------------------------------------------------------------
__device__ __forceinline__ float4 load_h4(const __half* base, size_t row, int lane)
{
    uint2 u = __ldg(reinterpret_cast<const uint2*>(base + row * DD) + lane);
    __half2 h0 = *reinterpret_cast<__half2*>(&u.x);
    __half2 h1 = *reinterpret_cast<__half2*>(&u.y);
    float2 f0 = __half22float2(h0);
    float2 f1 = __half22float2(h1);
    return make_float4(f0.x, f0.y, f1.x, f1.y);
}

__global__ __launch_bounds__(256)
void gather_kernel(const float4* __restrict__ ut, const float4* __restrict__ gt,
                   const int* __restrict__ ui, const int* __restrict__ pg,
                   const int* __restrict__ ng, float4* __restrict__ out)
{
    int t = blockIdx.x * blockDim.x + threadIdx.x;
    if (t >= BB * 16) return;
    int b    = t >> 4;
    int lane = t & 15;

    int u = ui[b];
    size_t gp = (size_t)NUM_USER + pg[b];
    size_t gn = (size_t)NUM_USER + ng[b];

    const float s = 0.25f;

    {
        float4 t0 = ut[(size_t)u * 16 + lane];
        float4 f1 = load_h4(g_e1, (size_t)u, lane);
        float4 f2 = load_h4(g_e2, (size_t)u, lane);
        float4 f3 = load_h4(g_e3, (size_t)u, lane);
        out[((size_t)0 * BB + b) * 16 + lane] = make_float4(
            (t0.x + f1.x + f2.x + f3.x) * s, (t0.y + f1.y + f2.y + f3.y) * s,
            (t0.z + f1.z + f2.z + f3.z) * s, (t0.w + f1.w + f2.w + f3.w) * s);
        out[((size_t)3 * BB + b) * 16 + lane] = t0;
    }
    {
        float4 t0 = gt[(gp - NUM_USER) * 16 + lane];
        float4 f1 = load_h4(g_e1, gp, lane);
        float4 f2 = load_h4(g_e2, gp, lane);
        float4 f3 = load_h4(g_e3, gp, lane);
        out[((size_t)1 * BB + b) * 16 + lane] = make_float4(
            (t0.x + f1.x + f2.x + f3.x) * s, (t0.y + f1.y + f2.y + f3.y) * s,
            (t0.z + f1.z + f2.z + f3.z) * s, (t0.w + f1.w + f2.w + f3.w) * s);
        out[((size_t)4 * BB + b) * 16 + lane] = t0;
    }
    {
        float4 t0 = gt[(gn - NUM_USER) * 16 + lane];
        float4 f1 = load_h4(g_e1, gn, lane);
        float4 f2 = load_h4(g_e2, gn, lane);
        float4 f3 = load_h4(g_e3, gn, lane);
        out[((size_t)2 * BB + b) * 16 + lane] = make_float4(
            (t0.x + f1.x + f2.x + f3.x) * s, (t0.y + f1.y + f2.y + f3.y) * s,
            (t0.z + f1.z + f2.z + f3.z) * s, (t0.w + f1.w + f2.w + f3.w) * s);
        out[((size_t)5 * BB + b) * 16 + lane] = t0;
    }
}

// ---------------------------------------------------------------------------
extern "C" void kernel_launch(void* const* d_in, const int* in_sizes, int n_in,
                              void* d_out, int out_size)
{
    const float* user_table  = (const float*)d_in[0];
    const float* group_table = (const float*)d_in[1];
    const float* adj_vals    = (const float*)d_in[2];
    const int*   rows        = (const int*)  d_in[3];
    const int*   cols        = (const int*)  d_in[4];
    const int*   user_inputs = (const int*)  d_in[5];
    const int*   pos_groups  = (const int*)  d_in[6];
    const int*   neg_groups  = (const int*)  d_in[7];

    __half* e0 = nullptr, * e1 = nullptr, * e2 = nullptr, * e3 = nullptr;
    cudaGetSymbolAddress((void**)&e0, g_e0);
    cudaGetSymbolAddress((void**)&e1, g_e1);
    cudaGetSymbolAddress((void**)&e2, g_e2);
    cudaGetSymbolAddress((void**)&e3, g_e3);

    const int TB = 256;

    convert_kernel<<<(NROWS * 8 + TB - 1) / TB, TB>>>(
        (const float4*)user_table, (const float4*)group_table);

    hist_kernel<<<(EDGES / 4 + TB - 1) / TB, TB>>>((const int4*)rows);
    scan1_kernel<<<NBLK_SCAN, TB>>>();
    scan3_kernel<<<NBLK_SCAN, TB>>>();
    scatter_kernel<<<(EDGES + TB - 1) / TB, TB>>>(rows, cols, adj_vals);

    const int grid_spmm = (NROWS * 8 + TB - 1) / TB;   // 7813

    spmm_csr_h_kernel<<<grid_spmm, TB>>>((const int4*)e0, (int4*)e1);
    spmm_csr_h_kernel<<<grid_spmm, TB>>>((const int4*)e1, (int4*)e2);
    spmm_csr_h_kernel<<<grid_spmm, TB>>>((const int4*)e2, (int4*)e3);

    gather_kernel<<<(BB * 16 + TB - 1) / TB, TB>>>(
        (const float4*)user_table, (const float4*)group_table,
        user_inputs, pos_groups, neg_groups, (float4*)d_out);
}

// round 9
// speedup vs baseline: 1.3618x; 1.1928x over previous
#include <cuda_runtime.h>
#include <cuda_fp16.h>
#include <cstdint>

#define NUM_USER  200000
#define NUM_GROUP 50000
#define NROWS     (NUM_USER + NUM_GROUP)   // 250000
#define EDGES     4000000
#define DD        64
#define BB        8192

__device__ __forceinline__ int h2_as_int(__half2 h) {
    return *reinterpret_cast<int*>(&h);
}

// ---- scratch (__device__ globals; no cudaMalloc allowed) -------------------
__device__ __half g_e0[(size_t)NROWS * DD];   // fp16 concat(tables)
__device__ __half g_e1[(size_t)NROWS * DD];
__device__ __half g_e2[(size_t)NROWS * DD];
__device__ int2   g_pairs[EDGES];             // (col, val-bits) sorted by row
__device__ int    g_counts[NROWS];
__device__ int    g_row_ptr[NROWS + 1];
__device__ int    g_cursor[NROWS];
__device__ int    g_s1done;

#define SCAN_ELEMS 2048
#define NBLK_SCAN  ((NROWS + SCAN_ELEMS - 1) / SCAN_ELEMS)   // 123
__device__ int   g_blocksums[NBLK_SCAN];
__device__ int   g_blockoff [NBLK_SCAN];

// ---------------------------------------------------------------------------
// 0) convert fp32 tables -> fp16 concat buffer; zero histogram + ticket
// ---------------------------------------------------------------------------
__global__ __launch_bounds__(256)
void convert_kernel(const float4* __restrict__ ut, const float4* __restrict__ gt)
{
    int i = blockIdx.x * blockDim.x + threadIdx.x;   // one int4 (8 halves)
    if (i < NROWS) g_counts[i] = 0;
    if (i == 0)    g_s1done = 0;
    if (i >= NROWS * 8) return;
    const int USER8 = NUM_USER * 8;
    float4 lo, hi;
    if (i < USER8) { lo = ut[(size_t)i * 2]; hi = ut[(size_t)i * 2 + 1]; }
    else { size_t j = i - USER8; lo = gt[j * 2]; hi = gt[j * 2 + 1]; }
    int4 o;
    o.x = h2_as_int(__floats2half2_rn(lo.x, lo.y));
    o.y = h2_as_int(__floats2half2_rn(lo.z, lo.w));
    o.z = h2_as_int(__floats2half2_rn(hi.x, hi.y));
    o.w = h2_as_int(__floats2half2_rn(hi.z, hi.w));
    reinterpret_cast<int4*>(g_e0)[i] = o;
}

// ---------------------------------------------------------------------------
// 1) histogram rows (int4-vectorized read)
// ---------------------------------------------------------------------------
__global__ __launch_bounds__(256)
void hist_kernel(const int4* __restrict__ rows4)
{
    int i = blockIdx.x * blockDim.x + threadIdx.x;
    if (i >= EDGES / 4) return;
    int4 r = rows4[i];
    atomicAdd(&g_counts[r.x], 1);
    atomicAdd(&g_counts[r.y], 1);
    atomicAdd(&g_counts[r.z], 1);
    atomicAdd(&g_counts[r.w], 1);
}

// ---------------------------------------------------------------------------
// 2a) per-block sums + (last block via ticket) scan of the 123 block sums
// ---------------------------------------------------------------------------
__global__ __launch_bounds__(256)
void scan1_kernel()
{
    __shared__ int sh[256];
    __shared__ int sh_last;
    int tid  = threadIdx.x;
    int base = blockIdx.x * SCAN_ELEMS + tid * 8;
    int s = 0;
    #pragma unroll
    for (int j = 0; j < 8; j++) {
        int i = base + j;
        s += (i < NROWS) ? g_counts[i] : 0;
    }
    sh[tid] = s;
    __syncthreads();
    for (int off = 128; off > 0; off >>= 1) {
        if (tid < off) sh[tid] += sh[tid + off];
        __syncthreads();
    }
    if (tid == 0) {
        g_blocksums[blockIdx.x] = sh[0];
        __threadfence();
        int t = atomicAdd(&g_s1done, 1);
        sh_last = (t == gridDim.x - 1);
    }
    __syncthreads();
    if (sh_last) {
        __shared__ int sc[128];
        if (tid < 128) {
            int v = (tid < NBLK_SCAN) ? g_blocksums[tid] : 0;
            sc[tid] = v;
            __syncthreads();
            for (int off = 1; off < 128; off <<= 1) {
                int t2 = (tid >= off) ? sc[tid - off] : 0;
                __syncthreads();
                sc[tid] += t2;
                __syncthreads();
            }
            if (tid < NBLK_SCAN) g_blockoff[tid] = sc[tid] - v;
        }
    }
}

// 2b) intra-block exclusive scan + offset -> row_ptr & cursor
__global__ __launch_bounds__(256)
void scan3_kernel()
{
    __shared__ int sh[256];
    int tid  = threadIdx.x;
    int base = blockIdx.x * SCAN_ELEMS + tid * 8;
    int v[8];
    int s = 0;
    #pragma unroll
    for (int j = 0; j < 8; j++) {
        int i = base + j;
        v[j] = (i < NROWS) ? g_counts[i] : 0;
        s += v[j];
    }
    sh[tid] = s;
    __syncthreads();
    for (int off = 1; off < 256; off <<= 1) {
        int t = (tid >= off) ? sh[tid - off] : 0;
        __syncthreads();
        sh[tid] += t;
        __syncthreads();
    }
    int excl = sh[tid] - s;
    int run  = g_blockoff[blockIdx.x] + excl;
    #pragma unroll
    for (int j = 0; j < 8; j++) {
        int i = base + j;
        if (i < NROWS) { g_row_ptr[i] = run; g_cursor[i] = run; }
        run += v[j];
    }
    if (blockIdx.x == 0 && tid == 0) g_row_ptr[NROWS] = EDGES;
}

// ---------------------------------------------------------------------------
// 3) scatter edges into row-sorted order
// ---------------------------------------------------------------------------
__global__ __launch_bounds__(256)
void scatter_kernel(const int* __restrict__ rows, const int* __restrict__ cols,
                    const float* __restrict__ vals)
{
    int e = blockIdx.x * blockDim.x + threadIdx.x;
    if (e >= EDGES) return;
    int r   = rows[e];
    int pos = atomicAdd(&g_cursor[r], 1);
    g_pairs[pos] = make_int2(cols[e], __float_as_int(vals[e]));
}

// ---------------------------------------------------------------------------
// 4) CSR spmm, fp16 storage / fp32 accumulation (R4 known-good form).
//    8 threads per row; each owns 8 halves (one int4). Unroll 2.
// ---------------------------------------------------------------------------
__device__ __forceinline__ void acc_fma8(float* a, int4 x, float v)
{
    __half2* h = reinterpret_cast<__half2*>(&x);
    #pragma unroll
    for (int i = 0; i < 4; i++) {
        float2 f = __half22float2(h[i]);
        a[2*i]   = fmaf(v, f.x, a[2*i]);
        a[2*i+1] = fmaf(v, f.y, a[2*i+1]);
    }
}

__global__ __launch_bounds__(256)
void spmm_csr_h_kernel(const int4* __restrict__ src, int4* __restrict__ dst)
{
    int t    = blockIdx.x * blockDim.x + threadIdx.x;
    int r    = t >> 3;
    int lane = t & 7;
    if (r >= NROWS) return;

    int p  = g_row_ptr[r];
    int pe = g_row_ptr[r + 1];

    float a[8];
    #pragma unroll
    for (int i = 0; i < 8; i++) a[i] = 0.f;

    for (; p + 2 <= pe; p += 2) {
        int2 q0 = __ldg(&g_pairs[p]);
        int2 q1 = __ldg(&g_pairs[p + 1]);
        int4 x0 = __ldg(&src[(size_t)q0.x * 8 + lane]);
        int4 x1 = __ldg(&src[(size_t)q1.x * 8 + lane]);
        acc_fma8(a, x0, __int_as_float(q0.y));
        acc_fma8(a, x1, __int_as_float(q1.y));
    }
    if (p < pe) {
        int2 q0 = __ldg(&g_pairs[p]);
        int4 x0 = __ldg(&src[(size_t)q0.x * 8 + lane]);
        acc_fma8(a, x0, __int_as_float(q0.y));
    }

    int4 o;
    o.x = h2_as_int(__floats2half2_rn(a[0], a[1]));
    o.y = h2_as_int(__floats2half2_rn(a[2], a[3]));
    o.z = h2_as_int(__floats2half2_rn(a[4], a[5]));
    o.w = h2_as_int(__floats2half2_rn(a[6], a[7]));
    dst[(size_t)r * 8 + lane] = o;
}

// ---------------------------------------------------------------------------
// 5) FUSED layer-3 + gather: for each of 3*BB output slots, compute the
//    layer-3 spmm row (over e2) on the fly, combine with e0/e1/e2, and write
//    both the propagated section and the raw-table section.
//    8 threads per slot; each owns 8 features (32 B of fp32 out = 2 float4).
// ---------------------------------------------------------------------------
__global__ __launch_bounds__(256)
void l3_gather_kernel(const float4* __restrict__ ut, const float4* __restrict__ gt,
                      const int* __restrict__ ui, const int* __restrict__ pg,
                      const int* __restrict__ ng, float4* __restrict__ out)
{
    int t    = blockIdx.x * blockDim.x + threadIdx.x;
    int slot = t >> 3;              // 0 .. 3*BB-1
    int lane = t & 7;               // owns features [lane*8, lane*8+8)
    if (slot >= 3 * BB) return;

    int sec = slot / BB;            // 0=user, 1=pos, 2=neg
    int b   = slot - sec * BB;

    int r;
    const float4* tab;
    int tabrow;
    if (sec == 0)      { tabrow = ui[b];             r = tabrow;            tab = ut; }
    else if (sec == 1) { tabrow = pg[b];             r = NUM_USER + tabrow; tab = gt; }
    else               { tabrow = ng[b];             r = NUM_USER + tabrow; tab = gt; }

    // ---- layer-3 spmm for row r over e2 (identical inner loop to spmm) ----
    int p  = __ldg(&g_row_ptr[r]);
    int pe = __ldg(&g_row_ptr[r + 1]);

    float a[8];
    #pragma unroll
    for (int i = 0; i < 8; i++) a[i] = 0.f;

    const int4* src = reinterpret_cast<const int4*>(g_e2);
    for (; p + 2 <= pe; p += 2) {
        int2 q0 = __ldg(&g_pairs[p]);
        int2 q1 = __ldg(&g_pairs[p + 1]);
        int4 x0 = __ldg(&src[(size_t)q0.x * 8 + lane]);
        int4 x1 = __ldg(&src[(size_t)q1.x * 8 + lane]);
        acc_fma8(a, x0, __int_as_float(q0.y));
        acc_fma8(a, x1, __int_as_float(q1.y));
    }
    if (p < pe) {
        int2 q0 = __ldg(&g_pairs[p]);
        int4 x0 = __ldg(&src[(size_t)q0.x * 8 + lane]);
        acc_fma8(a, x0, __int_as_float(q0.y));
    }

    // ---- e0 (exact fp32 from table), e1, e2 rows ----
    float4 t0a = __ldg(&tab[(size_t)tabrow * 16 + lane * 2]);
    float4 t0b = __ldg(&tab[(size_t)tabrow * 16 + lane * 2 + 1]);

    int4 h1 = __ldg(&reinterpret_cast<const int4*>(g_e1)[(size_t)r * 8 + lane]);
    int4 h2 = __ldg(&reinterpret_cast<const int4*>(g_e2)[(size_t)r * 8 + lane]);
    float f1[8], f2[8];
    {
        __half2* hh1 = reinterpret_cast<__half2*>(&h1);
        __half2* hh2 = reinterpret_cast<__half2*>(&h2);
        #pragma unroll
        for (int i = 0; i < 4; i++) {
            float2 u1 = __half22float2(hh1[i]);
            float2 u2 = __half22float2(hh2[i]);
            f1[2*i] = u1.x; f1[2*i+1] = u1.y;
            f2[2*i] = u2.x; f2[2*i+1] = u2.y;
        }
    }

    const float s = 0.25f;
    float4 oa = make_float4((t0a.x + f1[0] + f2[0] + a[0]) * s,
                            (t0a.y + f1[1] + f2[1] + a[1]) * s,
                            (t0a.z + f1[2] + f2[2] + a[2]) * s,
                            (t0a.w + f1[3] + f2[3] + a[3]) * s);
    float4 ob = make_float4((t0b.x + f1[4] + f2[4] + a[4]) * s,
                            (t0b.y + f1[5] + f2[5] + a[5]) * s,
                            (t0b.z + f1[6] + f2[6] + a[6]) * s,
                            (t0b.w + f1[7] + f2[7] + a[7]) * s);

    // propagated section (0/1/2) and raw-table section (3/4/5)
    size_t obase = ((size_t)sec * BB + b) * 16 + lane * 2;
    out[obase]     = oa;
    out[obase + 1] = ob;
    size_t tbase = ((size_t)(sec + 3) * BB + b) * 16 + lane * 2;
    out[tbase]     = t0a;
    out[tbase + 1] = t0b;
}

// ---------------------------------------------------------------------------
extern "C" void kernel_launch(void* const* d_in, const int* in_sizes, int n_in,
                              void* d_out, int out_size)
{
    const float* user_table  = (const float*)d_in[0];
    const float* group_table = (const float*)d_in[1];
    const float* adj_vals    = (const float*)d_in[2];
    const int*   rows        = (const int*)  d_in[3];
    const int*   cols        = (const int*)  d_in[4];
    const int*   user_inputs = (const int*)  d_in[5];
    const int*   pos_groups  = (const int*)  d_in[6];
    const int*   neg_groups  = (const int*)  d_in[7];

    __half* e0 = nullptr, * e1 = nullptr, * e2 = nullptr;
    cudaGetSymbolAddress((void**)&e0, g_e0);
    cudaGetSymbolAddress((void**)&e1, g_e1);
    cudaGetSymbolAddress((void**)&e2, g_e2);

    const int TB = 256;

    convert_kernel<<<(NROWS * 8 + TB - 1) / TB, TB>>>(
        (const float4*)user_table, (const float4*)group_table);

    hist_kernel<<<(EDGES / 4 + TB - 1) / TB, TB>>>((const int4*)rows);
    scan1_kernel<<<NBLK_SCAN, TB>>>();
    scan3_kernel<<<NBLK_SCAN, TB>>>();
    scatter_kernel<<<(EDGES + TB - 1) / TB, TB>>>(rows, cols, adj_vals);

    const int grid_spmm = (NROWS * 8 + TB - 1) / TB;   // 7813

    // Layers 1 and 2 (full-node spmm)
    spmm_csr_h_kernel<<<grid_spmm, TB>>>((const int4*)e0, (int4*)e1);
    spmm_csr_h_kernel<<<grid_spmm, TB>>>((const int4*)e1, (int4*)e2);

    // Layer 3 fused with the 6-way gather: only 3*BB rows computed
    l3_gather_kernel<<<(3 * BB * 8 + TB - 1) / TB, TB>>>(
        (const float4*)user_table, (const float4*)group_table,
        user_inputs, pos_groups, neg_groups, (float4*)d_out);
}

// round 10
// speedup vs baseline: 1.3990x; 1.0272x over previous
#include <cuda_runtime.h>
#include <cuda_fp16.h>
#include <cstdint>

#define NUM_USER  200000
#define NUM_GROUP 50000
#define NROWS     (NUM_USER + NUM_GROUP)   // 250000
#define EDGES     4000000
#define DD        64
#define BB        8192

__device__ __forceinline__ int h2_as_int(__half2 h) {
    return *reinterpret_cast<int*>(&h);
}

// ---- scratch (__device__ globals; no cudaMalloc allowed) -------------------
__device__ __half g_e0[(size_t)NROWS * DD];   // fp16 concat(tables)
__device__ __half g_e1[(size_t)NROWS * DD];
__device__ __half g_e2[(size_t)NROWS * DD];
__device__ int2   g_pairs[EDGES];             // (col, val-bits) sorted by row
__device__ int    g_counts[NROWS];            // INVARIANT: zero at launch entry
__device__ int    g_row_ptr[NROWS + 1];
__device__ int    g_cursor[NROWS];

#define SCAN_ELEMS 2048
#define NBLK_SCAN  ((NROWS + SCAN_ELEMS - 1) / SCAN_ELEMS)   // 123
__device__ int   g_blockagg[NBLK_SCAN];       // aggregate+1; 0 = not ready

// ---------------------------------------------------------------------------
// 0) convert fp32 tables -> fp16 concat; ALSO: histogram rows (merged) and
//    zero the scan flags. g_counts is zero on entry (BSS-init / reset by scan).
// ---------------------------------------------------------------------------
__global__ __launch_bounds__(256)
void convert_hist_kernel(const float4* __restrict__ ut, const float4* __restrict__ gt,
                         const int4* __restrict__ rows4)
{
    int i = blockIdx.x * blockDim.x + threadIdx.x;   // one int4 (8 halves)
    if (i < NBLK_SCAN) g_blockagg[i] = 0;

    if (i < EDGES / 4) {
        int4 r = rows4[i];
        atomicAdd(&g_counts[r.x], 1);
        atomicAdd(&g_counts[r.y], 1);
        atomicAdd(&g_counts[r.z], 1);
        atomicAdd(&g_counts[r.w], 1);
    }

    if (i >= NROWS * 8) return;
    const int USER8 = NUM_USER * 8;
    float4 lo, hi;
    if (i < USER8) { lo = ut[(size_t)i * 2]; hi = ut[(size_t)i * 2 + 1]; }
    else { size_t j = i - USER8; lo = gt[j * 2]; hi = gt[j * 2 + 1]; }
    int4 o;
    o.x = h2_as_int(__floats2half2_rn(lo.x, lo.y));
    o.y = h2_as_int(__floats2half2_rn(lo.z, lo.w));
    o.z = h2_as_int(__floats2half2_rn(hi.x, hi.y));
    o.w = h2_as_int(__floats2half2_rn(hi.z, hi.w));
    reinterpret_cast<int4*>(g_e0)[i] = o;
}

// ---------------------------------------------------------------------------
// 1) single-pass scan (decoupled lookback, 123 blocks = wave-1 resident):
//    counts -> row_ptr & cursor; then re-zero counts for the next replay.
// ---------------------------------------------------------------------------
__global__ __launch_bounds__(256)
void scan_fused_kernel()
{
    __shared__ int sh[256];
    __shared__ int pref[256];
    int tid = threadIdx.x;
    int bid = blockIdx.x;
    int base = bid * SCAN_ELEMS + tid * 8;

    int v[8];
    int s = 0;
    #pragma unroll
    for (int j = 0; j < 8; j++) {
        int i = base + j;
        v[j] = (i < NROWS) ? g_counts[i] : 0;
        s += v[j];
    }
    sh[tid] = s;
    __syncthreads();
    // Hillis-Steele inclusive scan over 256 thread-totals
    for (int off = 1; off < 256; off <<= 1) {
        int t = (tid >= off) ? sh[tid - off] : 0;
        __syncthreads();
        sh[tid] += t;
        __syncthreads();
    }
    int total = sh[255];

    // publish this block's aggregate (+1 so 0 means "not ready")
    if (tid == 0) atomicExch(&g_blockagg[bid], total + 1);

    // lookback: sum all predecessor aggregates in parallel
    int part = 0;
    if (tid < bid) {
        int a;
        do { a = atomicAdd(&g_blockagg[tid], 0); } while (a == 0);
        part = a - 1;
    }
    pref[tid] = part;
    __syncthreads();
    for (int off = 128; off > 0; off >>= 1) {
        if (tid < off) pref[tid] += pref[tid + off];
        __syncthreads();
    }
    int offset = pref[0];

    int excl = sh[tid] - s;
    int run  = offset + excl;
    #pragma unroll
    for (int j = 0; j < 8; j++) {
        int i = base + j;
        if (i < NROWS) {
            g_row_ptr[i] = run;
            g_cursor[i]  = run;
            g_counts[i]  = 0;      // restore invariant for next launch/replay
        }
        run += v[j];
    }
    if (bid == 0 && tid == 0) g_row_ptr[NROWS] = EDGES;
}

// ---------------------------------------------------------------------------
// 2) scatter edges into row-sorted order
// ---------------------------------------------------------------------------
__global__ __launch_bounds__(256)
void scatter_kernel(const int* __restrict__ rows, const int* __restrict__ cols,
                    const float* __restrict__ vals)
{
    int e = blockIdx.x * blockDim.x + threadIdx.x;
    if (e >= EDGES) return;
    int r   = rows[e];
    int pos = atomicAdd(&g_cursor[r], 1);
    g_pairs[pos] = make_int2(cols[e], __float_as_int(vals[e]));
}

// ---------------------------------------------------------------------------
// 3) CSR spmm, fp16 storage / fp32 accumulation (known-good form, untouched).
// ---------------------------------------------------------------------------
__device__ __forceinline__ void acc_fma8(float* a, int4 x, float v)
{
    __half2* h = reinterpret_cast<__half2*>(&x);
    #pragma unroll
    for (int i = 0; i < 4; i++) {
        float2 f = __half22float2(h[i]);
        a[2*i]   = fmaf(v, f.x, a[2*i]);
        a[2*i+1] = fmaf(v, f.y, a[2*i+1]);
    }
}

__global__ __launch_bounds__(256)
void spmm_csr_h_kernel(const int4* __restrict__ src, int4* __restrict__ dst)
{
    int t    = blockIdx.x * blockDim.x + threadIdx.x;
    int r    = t >> 3;
    int lane = t & 7;
    if (r >= NROWS) return;

    int p  = g_row_ptr[r];
    int pe = g_row_ptr[r + 1];

    float a[8];
    #pragma unroll
    for (int i = 0; i < 8; i++) a[i] = 0.f;

    for (; p + 2 <= pe; p += 2) {
        int2 q0 = __ldg(&g_pairs[p]);
        int2 q1 = __ldg(&g_pairs[p + 1]);
        int4 x0 = __ldg(&src[(size_t)q0.x * 8 + lane]);
        int4 x1 = __ldg(&src[(size_t)q1.x * 8 + lane]);
        acc_fma8(a, x0, __int_as_float(q0.y));
        acc_fma8(a, x1, __int_as_float(q1.y));
    }
    if (p < pe) {
        int2 q0 = __ldg(&g_pairs[p]);
        int4 x0 = __ldg(&src[(size_t)q0.x * 8 + lane]);
        acc_fma8(a, x0, __int_as_float(q0.y));
    }

    int4 o;
    o.x = h2_as_int(__floats2half2_rn(a[0], a[1]));
    o.y = h2_as_int(__floats2half2_rn(a[2], a[3]));
    o.z = h2_as_int(__floats2half2_rn(a[4], a[5]));
    o.w = h2_as_int(__floats2half2_rn(a[6], a[7]));
    dst[(size_t)r * 8 + lane] = o;
}

// ---------------------------------------------------------------------------
// 4) FUSED layer-3 + gather (unchanged from R9 win)
// ---------------------------------------------------------------------------
__global__ __launch_bounds__(256)
void l3_gather_kernel(const float4* __restrict__ ut, const float4* __restrict__ gt,
                      const int* __restrict__ ui, const int* __restrict__ pg,
                      const int* __restrict__ ng, float4* __restrict__ out)
{
    int t    = blockIdx.x * blockDim.x + threadIdx.x;
    int slot = t >> 3;              // 0 .. 3*BB-1
    int lane = t & 7;               // owns features [lane*8, lane*8+8)
    if (slot >= 3 * BB) return;

    int sec = slot / BB;            // 0=user, 1=pos, 2=neg
    int b   = slot - sec * BB;

    int r;
    const float4* tab;
    int tabrow;
    if (sec == 0)      { tabrow = ui[b]; r = tabrow;            tab = ut; }
    else if (sec == 1) { tabrow = pg[b]; r = NUM_USER + tabrow; tab = gt; }
    else               { tabrow = ng[b]; r = NUM_USER + tabrow; tab = gt; }

    int p  = __ldg(&g_row_ptr[r]);
    int pe = __ldg(&g_row_ptr[r + 1]);

    float a[8];
    #pragma unroll
    for (int i = 0; i < 8; i++) a[i] = 0.f;

    const int4* src = reinterpret_cast<const int4*>(g_e2);
    for (; p + 2 <= pe; p += 2) {
        int2 q0 = __ldg(&g_pairs[p]);
        int2 q1 = __ldg(&g_pairs[p + 1]);
        int4 x0 = __ldg(&src[(size_t)q0.x * 8 + lane]);
        int4 x1 = __ldg(&src[(size_t)q1.x * 8 + lane]);
        acc_fma8(a, x0, __int_as_float(q0.y));
        acc_fma8(a, x1, __int_as_float(q1.y));
    }
    if (p < pe) {
        int2 q0 = __ldg(&g_pairs[p]);
        int4 x0 = __ldg(&src[(size_t)q0.x * 8 + lane]);
        acc_fma8(a, x0, __int_as_float(q0.y));
    }

    float4 t0a = __ldg(&tab[(size_t)tabrow * 16 + lane * 2]);
    float4 t0b = __ldg(&tab[(size_t)tabrow * 16 + lane * 2 + 1]);

    int4 h1 = __ldg(&reinterpret_cast<const int4*>(g_e1)[(size_t)r * 8 + lane]);
    int4 h2 = __ldg(&reinterpret_cast<const int4*>(g_e2)[(size_t)r * 8 + lane]);
    float f1[8], f2[8];
    {
        __half2* hh1 = reinterpret_cast<__half2*>(&h1);
        __half2* hh2 = reinterpret_cast<__half2*>(&h2);
        #pragma unroll
        for (int i = 0; i < 4; i++) {
            float2 u1 = __half22float2(hh1[i]);
            float2 u2 = __half22float2(hh2[i]);
            f1[2*i] = u1.x; f1[2*i+1] = u1.y;
            f2[2*i] = u2.x; f2[2*i+1] = u2.y;
        }
    }

    const float s = 0.25f;
    float4 oa = make_float4((t0a.x + f1[0] + f2[0] + a[0]) * s,
                            (t0a.y + f1[1] + f2[1] + a[1]) * s,
                            (t0a.z + f1[2] + f2[2] + a[2]) * s,
                            (t0a.w + f1[3] + f2[3] + a[3]) * s);
    float4 ob = make_float4((t0b.x + f1[4] + f2[4] + a[4]) * s,
                            (t0b.y + f1[5] + f2[5] + a[5]) * s,
                            (t0b.z + f1[6] + f2[6] + a[6]) * s,
                            (t0b.w + f1[7] + f2[7] + a[7]) * s);

    size_t obase = ((size_t)sec * BB + b) * 16 + lane * 2;
    out[obase]     = oa;
    out[obase + 1] = ob;
    size_t tbase = ((size_t)(sec + 3) * BB + b) * 16 + lane * 2;
    out[tbase]     = t0a;
    out[tbase + 1] = t0b;
}

// ---------------------------------------------------------------------------
extern "C" void kernel_launch(void* const* d_in, const int* in_sizes, int n_in,
                              void* d_out, int out_size)
{
    const float* user_table  = (const float*)d_in[0];
    const float* group_table = (const float*)d_in[1];
    const float* adj_vals    = (const float*)d_in[2];
    const int*   rows        = (const int*)  d_in[3];
    const int*   cols        = (const int*)  d_in[4];
    const int*   user_inputs = (const int*)  d_in[5];
    const int*   pos_groups  = (const int*)  d_in[6];
    const int*   neg_groups  = (const int*)  d_in[7];

    __half* e0 = nullptr, * e1 = nullptr, * e2 = nullptr;
    cudaGetSymbolAddress((void**)&e0, g_e0);
    cudaGetSymbolAddress((void**)&e1, g_e1);
    cudaGetSymbolAddress((void**)&e2, g_e2);

    const int TB = 256;

    // prep: convert + hist (one pass), then single-pass scan, then scatter
    convert_hist_kernel<<<(NROWS * 8 + TB - 1) / TB, TB>>>(
        (const float4*)user_table, (const float4*)group_table,
        (const int4*)rows);
    scan_fused_kernel<<<NBLK_SCAN, TB>>>();
    scatter_kernel<<<(EDGES + TB - 1) / TB, TB>>>(rows, cols, adj_vals);

    const int grid_spmm = (NROWS * 8 + TB - 1) / TB;   // 7813

    // Layers 1 and 2 (full-node spmm)
    spmm_csr_h_kernel<<<grid_spmm, TB>>>((const int4*)e0, (int4*)e1);
    spmm_csr_h_kernel<<<grid_spmm, TB>>>((const int4*)e1, (int4*)e2);

    // Layer 3 fused with the 6-way gather
    l3_gather_kernel<<<(3 * BB * 8 + TB - 1) / TB, TB>>>(
        (const float4*)user_table, (const float4*)group_table,
        user_inputs, pos_groups, neg_groups, (float4*)d_out);
}

// round 11
// speedup vs baseline: 1.5037x; 1.0749x over previous
#include <cuda_runtime.h>
#include <cuda_fp16.h>
#include <cstdint>

#define NUM_USER  200000
#define NUM_GROUP 50000
#define NROWS     (NUM_USER + NUM_GROUP)   // 250000
#define EDGES     4000000
#define DD        64
#define BB        8192

__device__ __forceinline__ int h2_as_int(__half2 h) {
    return *reinterpret_cast<int*>(&h);
}

// ---- scratch (__device__ globals; no cudaMalloc allowed) -------------------
__device__ __half g_e0[(size_t)NROWS * DD];   // fp16 concat(tables)
__device__ __half g_e1[(size_t)NROWS * DD];
__device__ __half g_e2[(size_t)NROWS * DD];
__device__ int2   g_pairs[EDGES];             // (col, val-bits) sorted by row
__device__ int    g_counts[NROWS];            // INVARIANT: zero at launch entry
__device__ int    g_row_ptr[NROWS + 1];
__device__ int    g_cursor[NROWS];

#define SCAN_ELEMS 2048
#define NBLK_SCAN  ((NROWS + SCAN_ELEMS - 1) / SCAN_ELEMS)   // 123
__device__ int   g_blockagg[NBLK_SCAN];       // aggregate+1; 0 = not ready

// ---------------------------------------------------------------------------
// 0) convert fp32 tables -> fp16 concat; ALSO: histogram rows (merged) and
//    zero the scan flags. g_counts is zero on entry (BSS-init / reset by scan).
// ---------------------------------------------------------------------------
__global__ __launch_bounds__(256)
void convert_hist_kernel(const float4* __restrict__ ut, const float4* __restrict__ gt,
                         const int4* __restrict__ rows4)
{
    int i = blockIdx.x * blockDim.x + threadIdx.x;   // one int4 (8 halves)
    if (i < NBLK_SCAN) g_blockagg[i] = 0;

    if (i < EDGES / 4) {
        int4 r = rows4[i];
        atomicAdd(&g_counts[r.x], 1);
        atomicAdd(&g_counts[r.y], 1);
        atomicAdd(&g_counts[r.z], 1);
        atomicAdd(&g_counts[r.w], 1);
    }

    if (i >= NROWS * 8) return;
    const int USER8 = NUM_USER * 8;
    float4 lo, hi;
    if (i < USER8) { lo = ut[(size_t)i * 2]; hi = ut[(size_t)i * 2 + 1]; }
    else { size_t j = i - USER8; lo = gt[j * 2]; hi = gt[j * 2 + 1]; }
    int4 o;
    o.x = h2_as_int(__floats2half2_rn(lo.x, lo.y));
    o.y = h2_as_int(__floats2half2_rn(lo.z, lo.w));
    o.z = h2_as_int(__floats2half2_rn(hi.x, hi.y));
    o.w = h2_as_int(__floats2half2_rn(hi.z, hi.w));
    reinterpret_cast<int4*>(g_e0)[i] = o;
}

// ---------------------------------------------------------------------------
// 1) single-pass scan (decoupled lookback, 123 blocks = wave-1 resident):
//    counts -> row_ptr & cursor; then re-zero counts for the next replay.
// ---------------------------------------------------------------------------
__global__ __launch_bounds__(256)
void scan_fused_kernel()
{
    __shared__ int sh[256];
    __shared__ int pref[256];
    int tid = threadIdx.x;
    int bid = blockIdx.x;
    int base = bid * SCAN_ELEMS + tid * 8;

    int v[8];
    int s = 0;
    #pragma unroll
    for (int j = 0; j < 8; j++) {
        int i = base + j;
        v[j] = (i < NROWS) ? g_counts[i] : 0;
        s += v[j];
    }
    sh[tid] = s;
    __syncthreads();
    for (int off = 1; off < 256; off <<= 1) {
        int t = (tid >= off) ? sh[tid - off] : 0;
        __syncthreads();
        sh[tid] += t;
        __syncthreads();
    }
    int total = sh[255];

    if (tid == 0) atomicExch(&g_blockagg[bid], total + 1);

    int part = 0;
    if (tid < bid) {
        int a;
        do { a = atomicAdd(&g_blockagg[tid], 0); } while (a == 0);
        part = a - 1;
    }
    pref[tid] = part;
    __syncthreads();
    for (int off = 128; off > 0; off >>= 1) {
        if (tid < off) pref[tid] += pref[tid + off];
        __syncthreads();
    }
    int offset = pref[0];

    int excl = sh[tid] - s;
    int run  = offset + excl;
    #pragma unroll
    for (int j = 0; j < 8; j++) {
        int i = base + j;
        if (i < NROWS) {
            g_row_ptr[i] = run;
            g_cursor[i]  = run;
            g_counts[i]  = 0;
        }
        run += v[j];
    }
    if (bid == 0 && tid == 0) g_row_ptr[NROWS] = EDGES;
}

// ---------------------------------------------------------------------------
// 2) scatter edges into row-sorted order
// ---------------------------------------------------------------------------
__global__ __launch_bounds__(256)
void scatter_kernel(const int* __restrict__ rows, const int* __restrict__ cols,
                    const float* __restrict__ vals)
{
    int e = blockIdx.x * blockDim.x + threadIdx.x;
    if (e >= EDGES) return;
    int r   = rows[e];
    int pos = atomicAdd(&g_cursor[r], 1);
    g_pairs[pos] = make_int2(cols[e], __float_as_int(vals[e]));
}

// ---------------------------------------------------------------------------
// 3) CSR spmm, fp16 storage AND fp16 packed math (HFMA2).
//    8 threads per row; each owns 8 halves (one int4). Unroll 2.
//    Per-edge-thread: 1 LDG + v->half2 + 4 HFMA2  (was: 8 cvt + 8 FFMA).
// ---------------------------------------------------------------------------
__device__ __forceinline__ void acc_hfma8(__half2* acc, int4 x, __half2 vv)
{
    __half2* h = reinterpret_cast<__half2*>(&x);
    #pragma unroll
    for (int i = 0; i < 4; i++)
        acc[i] = __hfma2(h[i], vv, acc[i]);
}

__global__ __launch_bounds__(256)
void spmm_csr_h_kernel(const int4* __restrict__ src, int4* __restrict__ dst)
{
    int t    = blockIdx.x * blockDim.x + threadIdx.x;
    int r    = t >> 3;
    int lane = t & 7;
    if (r >= NROWS) return;

    int p  = g_row_ptr[r];
    int pe = g_row_ptr[r + 1];

    __half2 acc[4];
    #pragma unroll
    for (int i = 0; i < 4; i++) acc[i] = __half2half2(__ushort_as_half(0));

    for (; p + 2 <= pe; p += 2) {
        int2 q0 = __ldg(&g_pairs[p]);
        int2 q1 = __ldg(&g_pairs[p + 1]);
        int4 x0 = __ldg(&src[(size_t)q0.x * 8 + lane]);
        int4 x1 = __ldg(&src[(size_t)q1.x * 8 + lane]);
        __half2 v0 = __float2half2_rn(__int_as_float(q0.y));
        __half2 v1 = __float2half2_rn(__int_as_float(q1.y));
        acc_hfma8(acc, x0, v0);
        acc_hfma8(acc, x1, v1);
    }
    if (p < pe) {
        int2 q0 = __ldg(&g_pairs[p]);
        int4 x0 = __ldg(&src[(size_t)q0.x * 8 + lane]);
        __half2 v0 = __float2half2_rn(__int_as_float(q0.y));
        acc_hfma8(acc, x0, v0);
    }

    int4 o;
    o.x = h2_as_int(acc[0]);
    o.y = h2_as_int(acc[1]);
    o.z = h2_as_int(acc[2]);
    o.w = h2_as_int(acc[3]);
    dst[(size_t)r * 8 + lane] = o;
}

// ---------------------------------------------------------------------------
// 4) FUSED layer-3 + gather (fp32 accumulate kept — final output path)
// ---------------------------------------------------------------------------
__device__ __forceinline__ void acc_fma8(float* a, int4 x, float v)
{
    __half2* h = reinterpret_cast<__half2*>(&x);
    #pragma unroll
    for (int i = 0; i < 4; i++) {
        float2 f = __half22float2(h[i]);
        a[2*i]   = fmaf(v, f.x, a[2*i]);
        a[2*i+1] = fmaf(v, f.y, a[2*i+1]);
    }
}

__global__ __launch_bounds__(256)
void l3_gather_kernel(const float4* __restrict__ ut, const float4* __restrict__ gt,
                      const int* __restrict__ ui, const int* __restrict__ pg,
                      const int* __restrict__ ng, float4* __restrict__ out)
{
    int t    = blockIdx.x * blockDim.x + threadIdx.x;
    int slot = t >> 3;              // 0 .. 3*BB-1
    int lane = t & 7;               // owns features [lane*8, lane*8+8)
    if (slot >= 3 * BB) return;

    int sec = slot / BB;            // 0=user, 1=pos, 2=neg
    int b   = slot - sec * BB;

    int r;
    const float4* tab;
    int tabrow;
    if (sec == 0)      { tabrow = ui[b]; r = tabrow;            tab = ut; }
    else if (sec == 1) { tabrow = pg[b]; r = NUM_USER + tabrow; tab = gt; }
    else               { tabrow = ng[b]; r = NUM_USER + tabrow; tab = gt; }

    int p  = __ldg(&g_row_ptr[r]);
    int pe = __ldg(&g_row_ptr[r + 1]);

    float a[8];
    #pragma unroll
    for (int i = 0; i < 8; i++) a[i] = 0.f;

    const int4* src = reinterpret_cast<const int4*>(g_e2);
    for (; p + 2 <= pe; p += 2) {
        int2 q0 = __ldg(&g_pairs[p]);
        int2 q1 = __ldg(&g_pairs[p + 1]);
        int4 x0 = __ldg(&src[(size_t)q0.x * 8 + lane]);
        int4 x1 = __ldg(&src[(size_t)q1.x * 8 + lane]);
        acc_fma8(a, x0, __int_as_float(q0.y));
        acc_fma8(a, x1, __int_as_float(q1.y));
    }
    if (p < pe) {
        int2 q0 = __ldg(&g_pairs[p]);
        int4 x0 = __ldg(&src[(size_t)q0.x * 8 + lane]);
        acc_fma8(a, x0, __int_as_float(q0.y));
    }

    float4 t0a = __ldg(&tab[(size_t)tabrow * 16 + lane * 2]);
    float4 t0b = __ldg(&tab[(size_t)tabrow * 16 + lane * 2 + 1]);

    int4 h1 = __ldg(&reinterpret_cast<const int4*>(g_e1)[(size_t)r * 8 + lane]);
    int4 h2 = __ldg(&reinterpret_cast<const int4*>(g_e2)[(size_t)r * 8 + lane]);
    float f1[8], f2[8];
    {
        __half2* hh1 = reinterpret_cast<__half2*>(&h1);
        __half2* hh2 = reinterpret_cast<__half2*>(&h2);
        #pragma unroll
        for (int i = 0; i < 4; i++) {
            float2 u1 = __half22float2(hh1[i]);
            float2 u2 = __half22float2(hh2[i]);
            f1[2*i] = u1.x; f1[2*i+1] = u1.y;
            f2[2*i] = u2.x; f2[2*i+1] = u2.y;
        }
    }

    const float s = 0.25f;
    float4 oa = make_float4((t0a.x + f1[0] + f2[0] + a[0]) * s,
                            (t0a.y + f1[1] + f2[1] + a[1]) * s,
                            (t0a.z + f1[2] + f2[2] + a[2]) * s,
                            (t0a.w + f1[3] + f2[3] + a[3]) * s);
    float4 ob = make_float4((t0b.x + f1[4] + f2[4] + a[4]) * s,
                            (t0b.y + f1[5] + f2[5] + a[5]) * s,
                            (t0b.z + f1[6] + f2[6] + a[6]) * s,
                            (t0b.w + f1[7] + f2[7] + a[7]) * s);

    size_t obase = ((size_t)sec * BB + b) * 16 + lane * 2;
    out[obase]     = oa;
    out[obase + 1] = ob;
    size_t tbase = ((size_t)(sec + 3) * BB + b) * 16 + lane * 2;
    out[tbase]     = t0a;
    out[tbase + 1] = t0b;
}

// ---------------------------------------------------------------------------
extern "C" void kernel_launch(void* const* d_in, const int* in_sizes, int n_in,
                              void* d_out, int out_size)
{
    const float* user_table  = (const float*)d_in[0];
    const float* group_table = (const float*)d_in[1];
    const float* adj_vals    = (const float*)d_in[2];
    const int*   rows        = (const int*)  d_in[3];
    const int*   cols        = (const int*)  d_in[4];
    const int*   user_inputs = (const int*)  d_in[5];
    const int*   pos_groups  = (const int*)  d_in[6];
    const int*   neg_groups  = (const int*)  d_in[7];

    __half* e0 = nullptr, * e1 = nullptr, * e2 = nullptr;
    cudaGetSymbolAddress((void**)&e0, g_e0);
    cudaGetSymbolAddress((void**)&e1, g_e1);
    cudaGetSymbolAddress((void**)&e2, g_e2);

    const int TB = 256;

    convert_hist_kernel<<<(NROWS * 8 + TB - 1) / TB, TB>>>(
        (const float4*)user_table, (const float4*)group_table,
        (const int4*)rows);
    scan_fused_kernel<<<NBLK_SCAN, TB>>>();
    scatter_kernel<<<(EDGES + TB - 1) / TB, TB>>>(rows, cols, adj_vals);

    const int grid_spmm = (NROWS * 8 + TB - 1) / TB;   // 7813

    spmm_csr_h_kernel<<<grid_spmm, TB>>>((const int4*)e0, (int4*)e1);
    spmm_csr_h_kernel<<<grid_spmm, TB>>>((const int4*)e1, (int4*)e2);

    l3_gather_kernel<<<(3 * BB * 8 + TB - 1) / TB, TB>>>(
        (const float4*)user_table, (const float4*)group_table,
        user_inputs, pos_groups, neg_groups, (float4*)d_out);
}